// round 6
// baseline (speedup 1.0000x reference)
#include <cuda_runtime.h>
#include <stdint.h>

#define NUM_TOKENS 2048
#define HIDDEN     768
#define MAXW       20
#define NUM_CAND   40960
#define UNARY      1024
#define SPAN_DIM   2324     // 3*768 + 20
#define NTOP       512
#define NPAD       65536
#define GCHUNK     96

typedef unsigned long long ull;

// ---------------- device scratch ----------------
__device__ float g_P[NUM_TOKENS * 3072];   // [tok][0:1024)=H1a, [1024:2048)=H1b, [2048:3072)=HD
__device__ float g_tok_att[NUM_TOKENS];
__device__ float g_prior[MAXW];
__device__ float g_Cw[MAXW * UNARY];
__device__ ull   g_keys[NPAD];
__device__ float g_scores[NUM_CAND];
__device__ int   g_sorted_se[NUM_CAND];
__device__ int   g_pidx[NTOP];
__device__ int   g_hist[NUM_TOKENS];
__device__ int   g_base[NUM_TOKENS];      // mutable cursor for scatter
__device__ int   g_base0[NUM_TOKENS + 1]; // immutable group offsets
__device__ int   g_perm[NUM_CAND];

// ---------------- f32x2 packed helpers ----------------
__device__ __forceinline__ ull pack2(float lo, float hi) {
    ull r; asm("mov.b64 %0, {%1, %2};" : "=l"(r) : "f"(lo), "f"(hi)); return r;
}
__device__ __forceinline__ ull fma2(ull a, ull b, ull c) {
    ull d; asm("fma.rn.f32x2 %0, %1, %2, %3;" : "=l"(d) : "l"(a), "l"(b), "l"(c)); return d;
}
__device__ __forceinline__ float2 unpack2(ull v) {
    float2 f; asm("mov.b64 {%0, %1}, %2;" : "=f"(f.x), "=f"(f.y) : "l"(v)); return f;
}

// ---------------- combined zero: g_hist + key padding ----------------
__global__ void zero_kernel() {
    int i = blockIdx.x * 256 + threadIdx.x;
    if (i < NUM_TOKENS) g_hist[i] = 0;
    if (i < NPAD - NUM_CAND) g_keys[NUM_CAND + i] = ~0ull;
}

// ---------------- tok_att = hidden @ w_attn + b_attn ----------------
__global__ void tok_att_kernel(const float* __restrict__ hid,
                               const float* __restrict__ w,
                               const float* __restrict__ b) {
    int warp = (blockIdx.x * blockDim.x + threadIdx.x) >> 5;
    int lane = threadIdx.x & 31;
    if (warp >= NUM_TOKENS) return;
    float acc = 0.f;
    for (int k = lane; k < HIDDEN; k += 32)
        acc += hid[(size_t)warp * HIDDEN + k] * w[k];
    #pragma unroll
    for (int o = 16; o; o >>= 1) acc += __shfl_down_sync(0xffffffffu, acc, o);
    if (lane == 0) g_tok_att[warp] = acc + b[0];
}

// ---------------- width tables ----------------
__global__ void tables_kernel(const float* __restrict__ ew,
                              const float* __restrict__ ewp,
                              const float* __restrict__ W1,
                              const float* __restrict__ Wp1,
                              const float* __restrict__ bp1,
                              const float* __restrict__ Wp2,
                              const float* __restrict__ bp2) {
    int w = blockIdx.x;
    int tid = threadIdx.x;
    __shared__ float red[256];
    float local = 0.f;
    for (int u = tid; u < UNARY; u += 256) {
        float cw = 0.f, hp = 0.f;
        #pragma unroll
        for (int f = 0; f < MAXW; f++) {
            cw += ew [w * MAXW + f] * W1 [(size_t)(1536 + f) * UNARY + u];
            hp += ewp[w * MAXW + f] * Wp1[(size_t)f * UNARY + u];
        }
        g_Cw[w * UNARY + u] = cw;
        hp += bp1[u];
        hp = fmaxf(hp, 0.f);
        local += hp * Wp2[u];
    }
    red[tid] = local;
    __syncthreads();
    for (int s = 128; s; s >>= 1) {
        if (tid < s) red[tid] += red[tid + s];
        __syncthreads();
    }
    if (tid == 0) g_prior[w] = red[0] + bp2[0];
}

// ---------------- counting-sort permutation by start ----------------
__global__ void hist_kernel(const int* __restrict__ starts) {
    int c = blockIdx.x * 256 + threadIdx.x;
    if (c < NUM_CAND) atomicAdd(&g_hist[starts[c]], 1);
}
__global__ __launch_bounds__(1024) void scan_kernel() {
    __shared__ int a[2048], b[2048];
    int t = threadIdx.x;
    a[t] = g_hist[t]; a[t + 1024] = g_hist[t + 1024];
    __syncthreads();
    int* src = a; int* dst = b;
    for (int off = 1; off < 2048; off <<= 1) {
        #pragma unroll
        for (int q = 0; q < 2; q++) {
            int i = t + q * 1024;
            dst[i] = src[i] + (i >= off ? src[i - off] : 0);
        }
        __syncthreads();
        int* tmp = src; src = dst; dst = tmp;
    }
    int e0 = t ? src[t - 1] : 0;
    int e1 = src[t + 1023];
    g_base[t] = e0;  g_base[t + 1024] = e1;
    g_base0[t] = e0; g_base0[t + 1024] = e1;
    if (t == 1023) g_base0[2048] = src[2047];
}
__global__ void scatter_kernel(const int* __restrict__ starts) {
    int c = blockIdx.x * 256 + threadIdx.x;
    if (c < NUM_CAND) {
        int pos = atomicAdd(&g_base[starts[c]], 1);
        g_perm[pos] = c;
    }
}

// ---------------- SGEMM half: g_P[m0..m0+1024) = hidden @ Wcat, f32x2 ----------------
#define BM 128
#define BN 128
#define BK 16
__global__ __launch_bounds__(256, 2) void sgemm_kernel(const float* __restrict__ A,
                                                       const float* __restrict__ W1,
                                                       int m0) {
    __shared__ float As[2][BK][BM];
    __shared__ float Bs[2][BK][BN];
    int bm = m0 + blockIdx.y * BM, bn = blockIdx.x * BN;
    int tid = threadIdx.x;
    int tr = tid >> 4, tc = tid & 15;

    ull accp[8][4];
    #pragma unroll
    for (int i = 0; i < 8; i++)
        #pragma unroll
        for (int j = 0; j < 4; j++) accp[i][j] = 0ull;

    int a_row = tid >> 2;
    int a_col = (tid & 3) << 2;
    int b_k   = tid >> 5;
    int b_n   = (tid & 31) << 2;

    int n_global = bn + b_n;
    int seg_off = (n_global < 1024) ? 0 : (n_global < 2048 ? 768 : 1556);
    int col = n_global & 1023;

    float4 ra0, ra1, rb0, rb1;
    ra0 = *reinterpret_cast<const float4*>(&A[(size_t)(bm + a_row) * HIDDEN + a_col]);
    ra1 = *reinterpret_cast<const float4*>(&A[(size_t)(bm + a_row + 64) * HIDDEN + a_col]);
    rb0 = *reinterpret_cast<const float4*>(&W1[(size_t)(seg_off + b_k) * UNARY + col]);
    rb1 = *reinterpret_cast<const float4*>(&W1[(size_t)(seg_off + b_k + 8) * UNARY + col]);
    {
        As[0][a_col + 0][a_row] = ra0.x; As[0][a_col + 1][a_row] = ra0.y;
        As[0][a_col + 2][a_row] = ra0.z; As[0][a_col + 3][a_row] = ra0.w;
        As[0][a_col + 0][a_row + 64] = ra1.x; As[0][a_col + 1][a_row + 64] = ra1.y;
        As[0][a_col + 2][a_row + 64] = ra1.z; As[0][a_col + 3][a_row + 64] = ra1.w;
        *reinterpret_cast<float4*>(&Bs[0][b_k][b_n]) = rb0;
        *reinterpret_cast<float4*>(&Bs[0][b_k + 8][b_n]) = rb1;
    }
    __syncthreads();

    int buf = 0;
    for (int kt = 0; kt < HIDDEN; kt += BK) {
        bool more = (kt + BK) < HIDDEN;
        if (more) {
            int kn = kt + BK;
            ra0 = *reinterpret_cast<const float4*>(&A[(size_t)(bm + a_row) * HIDDEN + kn + a_col]);
            ra1 = *reinterpret_cast<const float4*>(&A[(size_t)(bm + a_row + 64) * HIDDEN + kn + a_col]);
            rb0 = *reinterpret_cast<const float4*>(&W1[(size_t)(seg_off + kn + b_k) * UNARY + col]);
            rb1 = *reinterpret_cast<const float4*>(&W1[(size_t)(seg_off + kn + b_k + 8) * UNARY + col]);
        }
        #pragma unroll
        for (int kk = 0; kk < BK; kk++) {
            float4 a0 = *reinterpret_cast<const float4*>(&As[buf][kk][tr * 8]);
            float4 a1 = *reinterpret_cast<const float4*>(&As[buf][kk][tr * 8 + 4]);
            const ull* brow = reinterpret_cast<const ull*>(&Bs[buf][kk][tc * 8]);
            ull b0 = brow[0], b1v = brow[1], b2v = brow[2], b3v = brow[3];
            float ra[8] = {a0.x, a0.y, a0.z, a0.w, a1.x, a1.y, a1.z, a1.w};
            #pragma unroll
            for (int i = 0; i < 8; i++) {
                ull aa = pack2(ra[i], ra[i]);
                accp[i][0] = fma2(aa, b0,  accp[i][0]);
                accp[i][1] = fma2(aa, b1v, accp[i][1]);
                accp[i][2] = fma2(aa, b2v, accp[i][2]);
                accp[i][3] = fma2(aa, b3v, accp[i][3]);
            }
        }
        if (more) {
            int nb = buf ^ 1;
            As[nb][a_col + 0][a_row] = ra0.x; As[nb][a_col + 1][a_row] = ra0.y;
            As[nb][a_col + 2][a_row] = ra0.z; As[nb][a_col + 3][a_row] = ra0.w;
            As[nb][a_col + 0][a_row + 64] = ra1.x; As[nb][a_col + 1][a_row + 64] = ra1.y;
            As[nb][a_col + 2][a_row + 64] = ra1.z; As[nb][a_col + 3][a_row + 64] = ra1.w;
            *reinterpret_cast<float4*>(&Bs[nb][b_k][b_n]) = rb0;
            *reinterpret_cast<float4*>(&Bs[nb][b_k + 8][b_n]) = rb1;
            __syncthreads();
            buf = nb;
        }
    }
    #pragma unroll
    for (int i = 0; i < 8; i++) {
        float2 v0 = unpack2(accp[i][0]), v1 = unpack2(accp[i][1]);
        float2 v2 = unpack2(accp[i][2]), v3 = unpack2(accp[i][3]);
        float4 w0 = make_float4(v0.x, v0.y, v1.x, v1.y);
        float4 w1 = make_float4(v2.x, v2.y, v3.x, v3.y);
        size_t rowoff = (size_t)(bm + tr * 8 + i) * 3072 + bn + tc * 8;
        *reinterpret_cast<float4*>(&g_P[rowoff])     = w0;
        *reinterpret_cast<float4*>(&g_P[rowoff + 4]) = w1;
    }
}

// ---------------- span_emb rows: one block per start token ----------------
__global__ __launch_bounds__(192) void emb_group_kernel(const float* __restrict__ hid,
                                                        const int* __restrict__ ends,
                                                        const float* __restrict__ ew,
                                                        float* __restrict__ out) {
    int s = blockIdx.x;
    int gbeg = g_base0[s], gend = g_base0[s + 1];
    if (gbeg >= gend) return;
    int tid = threadIdx.x;
    int wlim = min(MAXW - 1, NUM_TOKENS - 1 - s);

    __shared__ float sh_e[MAXW], sh_invD[MAXW];
    __shared__ int sh_c[GCHUNK], sh_w[GCHUNK];

    if (tid < 32) {
        float l = (tid <= wlim) ? g_tok_att[s + tid] : __int_as_float(0xff800000);
        float m = l;
        #pragma unroll
        for (int o = 16; o; o >>= 1) m = fmaxf(m, __shfl_xor_sync(0xffffffffu, m, o));
        float ex = (tid <= wlim) ? expf(l - m) : 0.f;
        float d = ex;
        #pragma unroll
        for (int o = 1; o < 32; o <<= 1) {
            float t2 = __shfl_up_sync(0xffffffffu, d, o);
            if (tid >= o) d += t2;
        }
        if (tid < MAXW) { sh_e[tid] = ex; sh_invD[tid] = 1.f / d; }
    }

    const float4* hid4 = reinterpret_cast<const float4*>(hid);
    const float4* ew4  = reinterpret_cast<const float4*>(ew);
    float4 v0 = hid4[(size_t)s * 192 + tid];

    for (int chunk = gbeg; chunk < gend; chunk += GCHUNK) {
        int csz = min(GCHUNK, gend - chunk);
        __syncthreads();
        for (int m = tid; m < csz; m += 192) {
            int c = g_perm[chunk + m];
            sh_c[m] = c;
            sh_w[m] = ends[c] - s;
        }
        __syncthreads();
        float4 acc = make_float4(0.f, 0.f, 0.f, 0.f);
        float4 v = v0;
        for (int i = 0; i <= wlim; i++) {
            if (i) v = hid4[(size_t)(s + i) * 192 + tid];
            float ei = sh_e[i];
            acc.x += ei * v.x; acc.y += ei * v.y; acc.z += ei * v.z; acc.w += ei * v.w;
            for (int m = 0; m < csz; m++) {
                if (sh_w[m] == i) {
                    float4* row4 = reinterpret_cast<float4*>(out + (size_t)sh_c[m] * SPAN_DIM);
                    __stcs(&row4[tid], v0);
                    __stcs(&row4[192 + tid], v);
                    float inv = sh_invD[i];
                    float4 at = make_float4(acc.x * inv, acc.y * inv, acc.z * inv, acc.w * inv);
                    __stcs(&row4[389 + tid], at);
                    if (tid < 5) __stcs(&row4[384 + tid], ew4[i * 5 + tid]);
                }
            }
        }
    }
}

// ---------------- score: one block per start token (lo: s<1005, hi: s>=1005) ----------------
__global__ __launch_bounds__(256) void score_group_kernel(const int* __restrict__ ends,
                                                          const float* __restrict__ b1,
                                                          const float* __restrict__ W2,
                                                          const float* __restrict__ b2v,
                                                          int hi) {
    int s = blockIdx.x;
    if ((s >= 1005) != (hi != 0)) return;
    int gbeg = g_base0[s], gend = g_base0[s + 1];
    if (gbeg >= gend) return;
    int tid = threadIdx.x, lane = tid & 31, wrp = tid >> 5;
    int wlim = min(MAXW - 1, NUM_TOKENS - 1 - s);

    __shared__ float sh_e[MAXW], sh_invD[MAXW], sh_prior[MAXW];
    __shared__ int sh_c[GCHUNK], sh_w[GCHUNK];
    __shared__ float red[8];

    if (tid < 32) {
        float l = (tid <= wlim) ? g_tok_att[s + tid] : __int_as_float(0xff800000);
        float m = l;
        #pragma unroll
        for (int o = 16; o; o >>= 1) m = fmaxf(m, __shfl_xor_sync(0xffffffffu, m, o));
        float ex = (tid <= wlim) ? expf(l - m) : 0.f;
        float d = ex;
        #pragma unroll
        for (int o = 1; o < 32; o <<= 1) {
            float t2 = __shfl_up_sync(0xffffffffu, d, o);
            if (tid >= o) d += t2;
        }
        if (tid < MAXW) {
            sh_e[tid] = ex; sh_invD[tid] = 1.f / d;
            sh_prior[tid] = g_prior[tid];
        }
    }

    const float4* P4 = reinterpret_cast<const float4*>(g_P);
    float4 base = P4[(size_t)s * 768 + tid];                 // H1a[s]
    {
        float4 bb = reinterpret_cast<const float4*>(b1)[tid];
        base.x += bb.x; base.y += bb.y; base.z += bb.z; base.w += bb.w;
    }
    float4 w2 = reinterpret_cast<const float4*>(W2)[tid];
    float b2s = b2v[0];

    for (int chunk = gbeg; chunk < gend; chunk += GCHUNK) {
        int csz = min(GCHUNK, gend - chunk);
        __syncthreads();
        for (int m = tid; m < csz; m += 256) {
            int c = g_perm[chunk + m];
            sh_c[m] = c;
            sh_w[m] = ends[c] - s;
        }
        __syncthreads();
        float4 acc = make_float4(0.f, 0.f, 0.f, 0.f);
        for (int i = 0; i <= wlim; i++) {
            float4 hd = P4[(size_t)(s + i) * 768 + 512 + tid];  // HD[s+i]
            float ei = sh_e[i];
            acc.x += ei * hd.x; acc.y += ei * hd.y; acc.z += ei * hd.z; acc.w += ei * hd.w;
            for (int m = 0; m < csz; m++) {
                if (sh_w[m] == i) {
                    int c = sh_c[m];
                    float4 h1b = P4[(size_t)(s + i) * 768 + 256 + tid];   // H1b[e], e=s+i
                    float4 cw  = reinterpret_cast<const float4*>(g_Cw)[i * 256 + tid];
                    float inv = sh_invD[i];
                    float4 pre;
                    pre.x = base.x + h1b.x + cw.x + acc.x * inv;
                    pre.y = base.y + h1b.y + cw.y + acc.y * inv;
                    pre.z = base.z + h1b.z + cw.z + acc.z * inv;
                    pre.w = base.w + h1b.w + cw.w + acc.w * inv;
                    float local = fmaxf(pre.x, 0.f) * w2.x + fmaxf(pre.y, 0.f) * w2.y
                                + fmaxf(pre.z, 0.f) * w2.z + fmaxf(pre.w, 0.f) * w2.w;
                    #pragma unroll
                    for (int o = 16; o; o >>= 1) local += __shfl_xor_sync(0xffffffffu, local, o);
                    if (lane == 0) red[wrp] = local;
                    __syncthreads();
                    if (tid == 0) {
                        float tot = 0.f;
                        #pragma unroll
                        for (int q = 0; q < 8; q++) tot += red[q];
                        float sc = tot + b2s + sh_prior[i];
                        g_scores[c] = sc;
                        unsigned u = __float_as_uint(sc);
                        u = (u & 0x80000000u) ? ~u : (u | 0x80000000u);
                        g_keys[c] = ((ull)(~u) << 32) | (unsigned)c;
                    }
                    __syncthreads();
                }
            }
        }
    }
}

// ---------------- bitonic sort, 8192-element smem chunks (dynamic smem) ----------------
#define SORT_SMEM (8192 * 8)
__global__ __launch_bounds__(1024) void bitonic_smem_full8k() {
    extern __shared__ ull sk[];
    int base = blockIdx.x * 8192, t = threadIdx.x;
    #pragma unroll
    for (int r = 0; r < 8; r++) sk[t + r * 1024] = g_keys[base + t + r * 1024];
    __syncthreads();
    for (int k = 2; k <= 8192; k <<= 1)
        for (int j = k >> 1; j > 0; j >>= 1) {
            #pragma unroll
            for (int q = 0; q < 4; q++) {
                int pI = t + q * 1024;
                int i = ((pI & ~(j - 1)) << 1) | (pI & (j - 1));
                bool dir = (((base + i) & k) == 0);
                ull a = sk[i], b = sk[i | j];
                if ((a > b) == dir) { sk[i] = b; sk[i | j] = a; }
            }
            __syncthreads();
        }
    #pragma unroll
    for (int r = 0; r < 8; r++) g_keys[base + t + r * 1024] = sk[t + r * 1024];
}

__global__ __launch_bounds__(1024) void bitonic_smem_tail8k(int k) {
    extern __shared__ ull sk[];
    int base = blockIdx.x * 8192, t = threadIdx.x;
    #pragma unroll
    for (int r = 0; r < 8; r++) sk[t + r * 1024] = g_keys[base + t + r * 1024];
    __syncthreads();
    for (int j = 4096; j > 0; j >>= 1) {
        #pragma unroll
        for (int q = 0; q < 4; q++) {
            int pI = t + q * 1024;
            int i = ((pI & ~(j - 1)) << 1) | (pI & (j - 1));
            bool dir = (((base + i) & k) == 0);
            ull a = sk[i], b = sk[i | j];
            if ((a > b) == dir) { sk[i] = b; sk[i | j] = a; }
        }
        __syncthreads();
    }
    #pragma unroll
    for (int r = 0; r < 8; r++) g_keys[base + t + r * 1024] = sk[t + r * 1024];
}

__global__ void bitonic_gstep(int j, int k) {
    int pI = blockIdx.x * blockDim.x + threadIdx.x;
    int i = ((pI & ~(j - 1)) << 1) | (pI & (j - 1));
    bool dir = ((i & k) == 0);
    ull a = g_keys[i], b = g_keys[i | j];
    if ((a > b) == dir) { g_keys[i] = b; g_keys[i | j] = a; }
}

__global__ void decorate_kernel(const int* __restrict__ starts,
                                const int* __restrict__ ends) {
    int pI = blockIdx.x * blockDim.x + threadIdx.x;
    if (pI < NUM_CAND) {
        int idx = (int)(g_keys[pI] & 0xffffffffull);
        g_sorted_se[pI] = (starts[idx] << 16) | ends[idx];
    }
}

// ---------------- serial greedy NMS + position sort + scalar outputs ----------------
__global__ __launch_bounds__(256) void nms_kernel(const int* __restrict__ starts,
                                                  const int* __restrict__ ends,
                                                  const int* __restrict__ spk,
                                                  float* __restrict__ out) {
    __shared__ int latest[NUM_TOKENS];
    __shared__ int earliest[NUM_TOKENS];
    __shared__ int chunk[2048];
    __shared__ ull akey[NTOP];
    __shared__ int aidx[NTOP];
    __shared__ int s_count;

    int tid = threadIdx.x, lane = tid & 31;
    for (int t = tid; t < NUM_TOKENS; t += 256) { latest[t] = -1; earliest[t] = NUM_TOKENS; }
    if (tid == 0) s_count = 0;
    __syncthreads();

    int count = 0, pos = 0;
    while (pos < NUM_CAND && count < NTOP) {
        int n = min(2048, NUM_CAND - pos);
        for (int t = tid; t < n; t += 256) chunk[t] = g_sorted_se[pos + t];
        __syncthreads();
        if (tid < 32) {
            for (int cI = 0; cI < n && count < NTOP; cI++) {
                int se = chunk[cI];
                int s = se >> 16, e = se & 0xffff;
                int t = s + lane;
                bool act = (lane <= e - s);
                bool c1 = act && (t > s) && (latest[t] > e);
                bool c2 = act && (t < e) && (earliest[t] < s);
                if (__ballot_sync(0xffffffffu, c1 || c2) == 0u) {
                    if (lane == 0) {
                        latest[s] = max(latest[s], e);
                        earliest[e] = min(earliest[e], s);
                        int idx = (int)(g_keys[pos + cI] & 0xffffffffull);
                        aidx[count] = idx;
                        akey[count] = (((ull)(s * (NUM_TOKENS + 1) + e)) << 10) | (unsigned)count;
                    }
                    count++;
                }
                __syncwarp();
            }
            if (lane == 0) s_count = count;
        }
        __syncthreads();
        count = s_count;
        pos += n;
    }
    __syncthreads();
    for (int r = tid; r < NTOP; r += 256)
        if (r >= count) { akey[r] = ~0ull; aidx[r] = 0; }
    __syncthreads();

    for (int k = 2; k <= NTOP; k <<= 1)
        for (int j = k >> 1; j > 0; j >>= 1) {
            int i = ((tid & ~(j - 1)) << 1) | (tid & (j - 1));
            bool dir = ((i & k) == 0);
            ull a = akey[i], b = akey[i | j];
            if ((a > b) == dir) {
                akey[i] = b; akey[i | j] = a;
                int x = aidx[i]; aidx[i] = aidx[i | j]; aidx[i | j] = x;
            }
            __syncthreads();
        }

    int first = aidx[0];
    const size_t base = (size_t)NUM_CAND * SPAN_DIM;
    const size_t emb_off = base + 3 * NTOP;
    const size_t sc_off = emb_off + (size_t)NTOP * SPAN_DIM;
    for (int r = tid; r < NTOP; r += 256) {
        int idx = (r < count) ? aidx[r] : first;
        int s = starts[idx], e = ends[idx];
        out[base + r]            = (float)idx;
        out[base + NTOP + r]     = (float)s;
        out[base + 2 * NTOP + r] = (float)e;
        out[sc_off + r]          = g_scores[idx];
        out[sc_off + NTOP + r]   = (float)spk[s];
        g_pidx[r] = idx;
    }
}

__global__ void gather_emb(float* __restrict__ out) {
    int r = blockIdx.x;
    int idx = g_pidx[r];
    const float* src = out + (size_t)idx * SPAN_DIM;
    float* dst = out + (size_t)NUM_CAND * SPAN_DIM + 3 * NTOP + (size_t)r * SPAN_DIM;
    for (int d = threadIdx.x; d < SPAN_DIM; d += 256) dst[d] = src[d];
}

// ---------------- launch (multi-stream, graph-capturable fork/join) ----------------
extern "C" void kernel_launch(void* const* d_in, const int* in_sizes, int n_in,
                              void* d_out, int out_size) {
    const float* hid    = (const float*)d_in[0];
    const int*   starts = (const int*)  d_in[1];
    const int*   ends   = (const int*)  d_in[2];
    const int*   spk    = (const int*)  d_in[3];
    const float* w_attn = (const float*)d_in[4];
    const float* b_attn = (const float*)d_in[5];
    const float* W1     = (const float*)d_in[6];
    const float* b1     = (const float*)d_in[7];
    const float* W2     = (const float*)d_in[8];
    const float* b2     = (const float*)d_in[9];
    const float* ew     = (const float*)d_in[10];
    const float* ewp    = (const float*)d_in[11];
    const float* Wp1    = (const float*)d_in[12];
    const float* bp1    = (const float*)d_in[13];
    const float* Wp2    = (const float*)d_in[14];
    const float* bp2    = (const float*)d_in[15];
    float* out = (float*)d_out;

    static cudaStream_t sB = 0, sC = 0;
    static cudaEvent_t evRoot = 0, evGL = 0, evGH = 0, evPerm = 0, evEmb = 0, evScore = 0;
    if (!sB) {
        cudaStreamCreateWithFlags(&sB, cudaStreamNonBlocking);
        cudaStreamCreateWithFlags(&sC, cudaStreamNonBlocking);
        cudaEventCreateWithFlags(&evRoot,  cudaEventDisableTiming);
        cudaEventCreateWithFlags(&evGL,    cudaEventDisableTiming);
        cudaEventCreateWithFlags(&evGH,    cudaEventDisableTiming);
        cudaEventCreateWithFlags(&evPerm,  cudaEventDisableTiming);
        cudaEventCreateWithFlags(&evEmb,   cudaEventDisableTiming);
        cudaEventCreateWithFlags(&evScore, cudaEventDisableTiming);
        cudaFuncSetAttribute(bitonic_smem_full8k,
                             cudaFuncAttributeMaxDynamicSharedMemorySize, SORT_SMEM);
        cudaFuncSetAttribute(bitonic_smem_tail8k,
                             cudaFuncAttributeMaxDynamicSharedMemorySize, SORT_SMEM);
    }

    cudaEventRecord(evRoot, 0);
    cudaStreamWaitEvent(sB, evRoot, 0);
    cudaStreamWaitEvent(sC, evRoot, 0);

    zero_kernel<<<96, 256, 0, sB>>>();                          // 1
    tok_att_kernel<<<256, 256, 0, sB>>>(hid, w_attn, b_attn);   // 2
    tables_kernel<<<20, 256>>>(ew, ewp, W1, Wp1, bp1, Wp2, bp2);// 3 (default)
    sgemm_kernel<<<dim3(24, 8), 256>>>(hid, W1, 0);             // 4 <- profiled slot
    cudaEventRecord(evGL, 0);
    sgemm_kernel<<<dim3(24, 8), 256>>>(hid, W1, 1024);          // 5
    cudaEventRecord(evGH, 0);

    hist_kernel<<<160, 256, 0, sB>>>(starts);                   // 6
    scan_kernel<<<1, 1024, 0, sB>>>();                          // 7
    scatter_kernel<<<160, 256, 0, sB>>>(starts);                // 8
    cudaEventRecord(evPerm, sB);
    emb_group_kernel<<<NUM_TOKENS, 192, 0, sB>>>(hid, ends, ew, out); // 9
    cudaEventRecord(evEmb, sB);

    cudaStreamWaitEvent(sC, evPerm, 0);
    cudaStreamWaitEvent(sC, evGL, 0);
    score_group_kernel<<<NUM_TOKENS, 256, 0, sC>>>(ends, b1, W2, b2, 0);  // 10
    cudaStreamWaitEvent(sC, evGH, 0);
    score_group_kernel<<<NUM_TOKENS, 256, 0, sC>>>(ends, b1, W2, b2, 1);  // 11
    cudaEventRecord(evScore, sC);

    cudaStreamWaitEvent(0, evScore, 0);
    bitonic_smem_full8k<<<8, 1024, SORT_SMEM>>>();
    for (int k = 16384; k <= 65536; k <<= 1) {
        for (int j = k >> 1; j >= 8192; j >>= 1)
            bitonic_gstep<<<128, 256>>>(j, k);
        bitonic_smem_tail8k<<<8, 1024, SORT_SMEM>>>(k);
    }
    decorate_kernel<<<160, 256>>>(starts, ends);
    nms_kernel<<<1, 256>>>(starts, ends, spk, out);
    cudaStreamWaitEvent(0, evEmb, 0);
    gather_emb<<<NTOP, 256>>>(out);
}